// round 2
// baseline (speedup 1.0000x reference)
#include <cuda_runtime.h>

// Problem constants (fixed by the reference setup)
#define S_DIM   4
#define B_DIM   2
#define F_DIM   64
#define P_DIM   16
#define HID     32
#define NPIX    131072      // T*H*W = 32*64*64, per (s,b) slice
#define BN_EPS  1e-5f

// ---------------------------------------------------------------------------
// Prepped weights (BN folded in), written by prep_kernel, read by main_kernel.
// Layout transposed so that o is contiguous: LDS.64 fetches an (o, o+1) pair.
// ---------------------------------------------------------------------------
__device__ float g_wsT[F_DIM][HID];   // ws[f][o] = w1[o][f] * scale[o]
__device__ float g_wpT[P_DIM][HID];   // wp[p][o] = w1[o][F+p] * scale[o]
__device__ float g_bias[HID];         // shift[o] = beta - mean*scale
__device__ float g_w2[HID];

__global__ void prep_kernel(const float* __restrict__ w1,
                            const float* __restrict__ gamma,
                            const float* __restrict__ beta,
                            const float* __restrict__ mean,
                            const float* __restrict__ var,
                            const float* __restrict__ w2) {
    __shared__ float s_scale[HID];
    int t = threadIdx.x;
    if (t < HID) {
        float sc = gamma[t] * rsqrtf(var[t] + BN_EPS);
        s_scale[t] = sc;
        g_bias[t]  = beta[t] - mean[t] * sc;
        g_w2[t]    = w2[t];
    }
    __syncthreads();
    const int KTOT = F_DIM + P_DIM;   // 80
    for (int i = t; i < HID * KTOT; i += blockDim.x) {
        int o = i / KTOT, c = i % KTOT;
        float v = w1[i] * s_scale[o];
        if (c < F_DIM) g_wsT[c][o] = v;
        else           g_wpT[c - F_DIM][o] = v;
    }
}

// ---------------------------------------------------------------------------
// Packed fp32x2 helpers (Blackwell sm_100+ packed fp32 pipe)
// ---------------------------------------------------------------------------
__device__ __forceinline__ unsigned long long pack2(float a, float b) {
    unsigned long long r;
    asm("mov.b64 %0, {%1, %2};" : "=l"(r) : "f"(a), "f"(b));
    return r;
}
__device__ __forceinline__ void unpack2(unsigned long long v, float& a, float& b) {
    asm("mov.b64 {%0, %1}, %2;" : "=f"(a), "=f"(b) : "l"(v));
}
__device__ __forceinline__ unsigned long long fma2(unsigned long long a,
                                                   unsigned long long b,
                                                   unsigned long long c) {
    unsigned long long r;
    asm("fma.rn.f32x2 %0, %1, %2, %3;" : "=l"(r) : "l"(a), "l"(b), "l"(c));
    return r;
}

// ---------------------------------------------------------------------------
// Fused kernel: per thread, 2 adjacent pixels (float2 loads/stores).
//  pass 1: h = Wf*x + Wp*p (BN-folded), relu, logits = w2.h  per s
//  softmax over s (4)  -> alpha
//  pass 2: out[f] = sum_s alpha_s * feats[s,f]  (second read of feats)
// h accumulators pack o-pairs in f32x2; x is duplicated once per f so
// every weight LDS.64 feeds two fma.f32x2 (one per pixel).
// ---------------------------------------------------------------------------
__global__ __launch_bounds__(256, 1)
void gssm_main_kernel(const float* __restrict__ feats,
                      const float* __restrict__ p_s,
                      float* __restrict__ out) {
    __shared__ float s_wsT[F_DIM][HID];   // 8 KB
    __shared__ float s_wpT[P_DIM][HID];   // 2 KB
    __shared__ float s_bias[HID];
    __shared__ float s_w2[HID];

    int t = threadIdx.x;
    for (int i = t; i < F_DIM * HID; i += 256)
        ((float*)s_wsT)[i] = ((const float*)g_wsT)[i];
    for (int i = t; i < P_DIM * HID; i += 256)
        ((float*)s_wpT)[i] = ((const float*)g_wpT)[i];
    if (t < HID) { s_bias[t] = g_bias[t]; s_w2[t] = g_w2[t]; }
    __syncthreads();

    // global pixel pair: each block covers 512 pixels (256 threads * 2 px)
    long n0 = (long)blockIdx.x * 512 + t * 2;
    int  b  = (int)(n0 / NPIX);
    int  m  = (int)(n0 % NPIX);

    // ---- p-feature contribution (shared across s) ----
    unsigned long long hp[HID / 2][2];
#pragma unroll
    for (int op = 0; op < HID / 2; op++) { hp[op][0] = 0ull; hp[op][1] = 0ull; }

    const float* pbase = p_s + (long)b * P_DIM * NPIX + m;
#pragma unroll
    for (int p = 0; p < P_DIM; p++) {
        float2 x = *(const float2*)(pbase + (long)p * NPIX);
        unsigned long long x0 = pack2(x.x, x.x);
        unsigned long long x1 = pack2(x.y, x.y);
#pragma unroll
        for (int op = 0; op < HID / 2; op++) {
            unsigned long long w = *(const unsigned long long*)&s_wpT[p][2 * op];
            hp[op][0] = fma2(w, x0, hp[op][0]);
            hp[op][1] = fma2(w, x1, hp[op][1]);
        }
    }

    // ---- per-s GEMM + BN + relu + w2 dot ----
    float logits[S_DIM][2];
#pragma unroll 1
    for (int s = 0; s < S_DIM; s++) {
        unsigned long long h[HID / 2][2];
#pragma unroll
        for (int op = 0; op < HID / 2; op++) { h[op][0] = hp[op][0]; h[op][1] = hp[op][1]; }

        const float* fb = feats + ((long)(s * B_DIM + b) * F_DIM) * NPIX + m;
#pragma unroll 8
        for (int f = 0; f < F_DIM; f++) {
            float2 x = *(const float2*)(fb + (long)f * NPIX);
            unsigned long long x0 = pack2(x.x, x.x);
            unsigned long long x1 = pack2(x.y, x.y);
#pragma unroll
            for (int op = 0; op < HID / 2; op++) {
                unsigned long long w = *(const unsigned long long*)&s_wsT[f][2 * op];
                h[op][0] = fma2(w, x0, h[op][0]);
                h[op][1] = fma2(w, x1, h[op][1]);
            }
        }

        float l0 = 0.f, l1 = 0.f;
#pragma unroll
        for (int op = 0; op < HID / 2; op++) {
            float b0 = s_bias[2 * op], b1 = s_bias[2 * op + 1];
            float w20 = s_w2[2 * op],  w21 = s_w2[2 * op + 1];
            float a, c;
            unpack2(h[op][0], a, c);
            l0 += fmaxf(a + b0, 0.f) * w20 + fmaxf(c + b1, 0.f) * w21;
            unpack2(h[op][1], a, c);
            l1 += fmaxf(a + b0, 0.f) * w20 + fmaxf(c + b1, 0.f) * w21;
        }
        logits[s][0] = l0;
        logits[s][1] = l1;
    }

    // ---- softmax over s (b2 is a constant shift -> cancels) ----
    float alpha[S_DIM][2];
#pragma unroll
    for (int px = 0; px < 2; px++) {
        float mx = fmaxf(fmaxf(logits[0][px], logits[1][px]),
                         fmaxf(logits[2][px], logits[3][px]));
        float sum = 0.f;
#pragma unroll
        for (int s = 0; s < S_DIM; s++) {
            float e = __expf(logits[s][px] - mx);
            alpha[s][px] = e;
            sum += e;
        }
        float inv = 1.f / sum;
#pragma unroll
        for (int s = 0; s < S_DIM; s++) alpha[s][px] *= inv;
    }

    // ---- write alpha: layout (B, S, NPIX), after the out region ----
    float* aout = out + (long)B_DIM * F_DIM * NPIX;
#pragma unroll
    for (int s = 0; s < S_DIM; s++) {
        *(float2*)(aout + ((long)b * S_DIM + s) * NPIX + m) =
            make_float2(alpha[s][0], alpha[s][1]);
    }

    // ---- pass 2: out[b,f] = sum_s alpha_s * feats[s,b,f] ----
    // unroll 8 -> 32 independent LDG.64 in flight to cover DRAM latency
    const float* fb0 = feats + ((long)b * F_DIM) * NPIX + m;   // s = 0
    const long   sstride = (long)B_DIM * F_DIM * NPIX;
#pragma unroll 8
    for (int f = 0; f < F_DIM; f++) {
        float2 acc = make_float2(0.f, 0.f);
#pragma unroll
        for (int s = 0; s < S_DIM; s++) {
            float2 x = *(const float2*)(fb0 + s * sstride + (long)f * NPIX);
            acc.x = fmaf(x.x, alpha[s][0], acc.x);
            acc.y = fmaf(x.y, alpha[s][1], acc.y);
        }
        *(float2*)(out + ((long)b * F_DIM + f) * NPIX + m) = acc;
    }
}

// ---------------------------------------------------------------------------
// Launch: inputs in metadata order:
//   0 feats, 1 p_s, 2 w1, 3 bn_gamma, 4 bn_beta, 5 bn_mean, 6 bn_var, 7 w2, 8 b2
// d_out = [out (B*F*NPIX floats)] ++ [alpha (B*S*NPIX floats)]
// ---------------------------------------------------------------------------
extern "C" void kernel_launch(void* const* d_in, const int* in_sizes, int n_in,
                              void* d_out, int out_size) {
    const float* feats = (const float*)d_in[0];
    const float* p_s   = (const float*)d_in[1];
    const float* w1    = (const float*)d_in[2];
    const float* gam   = (const float*)d_in[3];
    const float* bet   = (const float*)d_in[4];
    const float* mean  = (const float*)d_in[5];
    const float* var   = (const float*)d_in[6];
    const float* w2    = (const float*)d_in[7];
    float* outp = (float*)d_out;

    prep_kernel<<<1, 256>>>(w1, gam, bet, mean, var, w2);

    const long total_px = (long)B_DIM * NPIX;      // 262144
    int blocks = (int)(total_px / 512);            // 512 blocks
    gssm_main_kernel<<<blocks, 256>>>(feats, p_s, outp);
}